// round 13
// baseline (speedup 1.0000x reference)
#include <cuda_runtime.h>
#include <cuda_fp16.h>
#include <cstdint>

// ---------------- problem constants ----------------
#define M_SZ 32768
#define H_SZ 512
#define K_SZ 1024
#define NKC  32              // k32 chunks
#define NSTAGE 4
#define STAGE_BYTES 16384u   // A 4KB + 3 x B 4KB
#define PREF 3
#define EXROW 544            // epilogue exchange row stride (conflict-free)

#define SWZ64(x) ((uint32_t)(x) ^ ((((uint32_t)(x)) >> 3) & 0x30))

// A blocks: [m>>6][kc] 4KB  (64 rows x 64B, SW64 pre-swizzled)
// B blocks: [(kc*3+g)*8 + n>>6] 4KB (64 rows x 64B, SW64 pre-swizzled)
__device__ __align__(128) unsigned char g_A[(size_t)M_SZ * 2048];          // 64MB
__device__ __align__(128) unsigned char g_B[(size_t)3 * H_SZ * 2048];      // 3MB

// ---------------- helpers ----------------
__device__ __forceinline__ uint32_t smem_u32(const void* p) {
    uint32_t a;
    asm("{ .reg .u64 t; cvta.to.shared.u64 t, %1; cvt.u32.u64 %0, t; }" : "=r"(a) : "l"(p));
    return a;
}
__device__ __forceinline__ void ldmx4(uint32_t* r, uint32_t a) {
    asm volatile("ldmatrix.sync.aligned.m8n8.x4.shared.b16 {%0,%1,%2,%3}, [%4];"
        : "=r"(r[0]), "=r"(r[1]), "=r"(r[2]), "=r"(r[3]) : "r"(a));
}
__device__ __forceinline__ void mma16816(float* c, const uint32_t* a, uint32_t b0, uint32_t b1) {
    asm volatile("mma.sync.aligned.m16n8k16.row.col.f32.f16.f16.f32 "
        "{%0,%1,%2,%3}, {%4,%5,%6,%7}, {%8,%9}, {%0,%1,%2,%3};"
        : "+f"(c[0]), "+f"(c[1]), "+f"(c[2]), "+f"(c[3])
        : "r"(a[0]), "r"(a[1]), "r"(a[2]), "r"(a[3]), "r"(b0), "r"(b1));
}
__device__ __forceinline__ void mbar_init(uint32_t a, uint32_t cnt) {
    asm volatile("mbarrier.init.shared.b64 [%0], %1;" :: "r"(a), "r"(cnt) : "memory");
}
__device__ __forceinline__ void mbar_expect_tx(uint32_t a, uint32_t tx) {
    asm volatile("mbarrier.arrive.expect_tx.shared.b64 _, [%0], %1;" :: "r"(a), "r"(tx) : "memory");
}
__device__ __forceinline__ void mbar_arrive(uint32_t a) {
    asm volatile("mbarrier.arrive.shared.b64 _, [%0];" :: "r"(a) : "memory");
}
__device__ __forceinline__ void mbar_wait(uint32_t a, uint32_t parity) {
    asm volatile(
        "{\n\t.reg .pred P;\n\t"
        "WL%=:\n\t"
        "mbarrier.try_wait.parity.acquire.cta.shared::cta.b64 P, [%0], %1, 0x989680;\n\t"
        "@P bra WD%=;\n\t"
        "bra WL%=;\n\t"
        "WD%=:\n\t}"
        :: "r"(a), "r"(parity) : "memory");
}
__device__ __forceinline__ void bulk_g2s(uint32_t dst, const void* src, uint32_t bytes, uint32_t mbar) {
    asm volatile(
        "cp.async.bulk.shared::cluster.global.mbarrier::complete_tx::bytes [%0], [%1], %2, [%3];"
        :: "r"(dst), "l"(src), "r"(bytes), "r"(mbar) : "memory");
}

// ---------------- dummy (shifts ncu capture window onto lstm_gemm) ----------------
__global__ void dummy_k() {}

// ---------------- prep A: fp32 -> fp16, 64m x k32 blocks, SW64 pre-swizzled ----------------
__global__ __launch_bounds__(256)
void prep_a(const float* __restrict__ x, const float* __restrict__ h) {
    int gid = blockIdx.x * 256 + threadIdx.x;      // 8 elems per thread
    int m = gid >> 7;
    int k8 = (gid & 127) << 3;
    const float* s = (k8 < 512) ? (x + (size_t)m * 512 + k8)
                                : (h + (size_t)m * 512 + (k8 - 512));
    float4 v0 = ((const float4*)s)[0];
    float4 v1 = ((const float4*)s)[1];
    __half hh[8];
    hh[0] = __float2half_rn(v0.x); hh[1] = __float2half_rn(v0.y);
    hh[2] = __float2half_rn(v0.z); hh[3] = __float2half_rn(v0.w);
    hh[4] = __float2half_rn(v1.x); hh[5] = __float2half_rn(v1.y);
    hh[6] = __float2half_rn(v1.z); hh[7] = __float2half_rn(v1.w);
    size_t blk = ((size_t)(m >> 6) * NKC + (k8 >> 5)) * 4096;
    uint32_t ob = SWZ64(((m & 63) << 6) + ((k8 & 31) << 1));
    *(uint4*)(g_A + blk + ob) = *(uint4*)hh;
}

// ---------------- prep B: transpose + fp16, 4KB 64n-blocks, SW64 pre-swizzled ----------------
__global__ void prep_b(const float* __restrict__ Wxi, const float* __restrict__ Whi,
                       const float* __restrict__ Wxc, const float* __restrict__ Whc,
                       const float* __restrict__ Wxo, const float* __restrict__ Who) {
    __shared__ float tile[32][33];
    int n0 = blockIdx.x * 32;       // 0..1535 (gate-major n)
    int k0 = blockIdx.y * 32;       // 0..1023
    int g = n0 >> 9;
    int nc0 = n0 & 511;
    const float* Wx = (g == 0) ? Wxi : ((g == 1) ? Wxc : Wxo);
    const float* Wh = (g == 0) ? Whi : ((g == 1) ? Whc : Who);
    int tx = threadIdx.x, ty = threadIdx.y;   // 32 x 8
    #pragma unroll
    for (int r = ty; r < 32; r += 8) {
        int k = k0 + r;
        const float* W = (k < 512) ? (Wx + (size_t)k * 512) : (Wh + (size_t)(k - 512) * 512);
        tile[r][tx] = W[nc0 + tx];
    }
    __syncthreads();
    #pragma unroll
    for (int r = ty; r < 32; r += 8) {
        float v = tile[tx][r];                 // W[k0+tx][n0+r]
        int n = nc0 + r;                       // gate-local 0..511
        int k = k0 + tx;
        size_t blk = ((size_t)((k >> 5) * 3 + g) * 8 + (n >> 6)) * 4096;
        uint32_t ob = SWZ64(((n & 63) << 6) + ((k & 31) << 1));
        *(__half*)(g_B + blk + ob) = __float2half_rn(v);
    }
}

// ---------------- fused GEMM + epilogue ----------------
// CTA 64m x 64n x 3 gates; 384 threads = 12 warps, gate-split: warp wid -> gate wid/4,
// sub-quad (wid%4) = 2m x 2n, warp tile 32m x 32n of ONE gate. 2 CTAs/SM (85 regs).
// k32 chunks, 4 stages, bulk-copy, no syncthreads in mainloop; smem epilogue exchange.
__global__ __launch_bounds__(384, 2)
void lstm_gemm(const float* __restrict__ bxi, const float* __restrict__ bxc,
               const float* __restrict__ bxo,
               float* __restrict__ outh, float* __restrict__ outc) {
    extern __shared__ char dsm[];
    const uint32_t sb = (smem_u32(dsm) + 1023) & ~1023u;   // full[4]@0, empty[4]@64
    const uint32_t sd = sb + 1024;                          // stage data (4 x 16KB)
    char* dbase = dsm + (sb - smem_u32(dsm));               // aligned char* mirror
    char* exc = dbase + 1024;                               // epilogue exchange (reuses stages)

    const int tid  = threadIdx.x;
    const int lane = tid & 31;
    const int wid  = tid >> 5;
    const int g    = wid >> 2;       // gate 0=i, 1=c, 2=o
    const int sub  = wid & 3;
    const int wm   = sub >> 1;       // m offset 32*wm
    const int wn   = sub & 1;        // n offset 32*wn
    const int m0   = blockIdx.y << 6;
    const int n0   = blockIdx.x << 6;
    const int mb   = blockIdx.y;
    const int nb   = blockIdx.x;     // 64-col n-block (0..7)

    if (tid == 0) {
        #pragma unroll
        for (int s = 0; s < NSTAGE; ++s) {
            mbar_init(sb + 8 * s, 1);         // full: tx-based
            mbar_init(sb + 64 + 8 * s, 12);   // empty: 12 warp arrivals
        }
        asm volatile("fence.proxy.async.shared::cta;" ::: "memory");
    }
    __syncthreads();

    auto issue_chunk = [&](int c) {
        const int s = c & 3;
        const uint32_t mbar = sb + 8 * s;
        const uint32_t dst = sd + (uint32_t)s * STAGE_BYTES;
        mbar_expect_tx(mbar, STAGE_BYTES);
        bulk_g2s(dst, g_A + ((size_t)mb * NKC + c) * 4096, 4096u, mbar);
        #pragma unroll
        for (int gg = 0; gg < 3; ++gg)
            bulk_g2s(dst + 4096u * (1 + gg),
                     g_B + ((size_t)((c * 3 + gg) * 8) + nb) * 4096, 4096u, mbar);
    };

    if (tid == 0) {
        issue_chunk(0);
        issue_chunk(1);
        issue_chunk(2);
    }

    // ldmatrix bases (SW64, 64B rows); per-ks XOR 32
    uint32_t a_base[2];
    #pragma unroll
    for (int mt = 0; mt < 2; ++mt) {
        int row = (wm << 5) + (mt << 4) + (lane & 15);
        int ro  = row * 64 + ((lane >> 4) << 4);
        a_base[mt] = SWZ64(ro);
    }
    uint32_t b_base[2];
    #pragma unroll
    for (int ng = 0; ng < 2; ++ng) {
        int rr = (wn << 5) + (ng << 4) + (lane & 7) + (((lane >> 4) & 1) << 3);
        int ro = rr * 64 + (((lane >> 3) & 1) << 4);
        b_base[ng] = SWZ64(ro);
    }
    const uint32_t b_goff = 4096u * (1 + (uint32_t)g);

    float c[2][4][4];   // mt, nq, e -> 32 regs (single gate)
    #pragma unroll
    for (int mt = 0; mt < 2; ++mt)
        #pragma unroll
        for (int nq = 0; nq < 4; ++nq)
            #pragma unroll
            for (int e = 0; e < 4; ++e) c[mt][nq][e] = 0.0f;

    for (int ch = 0; ch < NKC; ++ch) {
        const int s = ch & 3;
        mbar_wait(sb + 8 * s, (ch >> 2) & 1);

        const uint32_t sA = sd + (uint32_t)s * STAGE_BYTES;
        const uint32_t sB = sA + b_goff;

        #pragma unroll
        for (int ks = 0; ks < 2; ++ks) {
            const uint32_t kx = (uint32_t)(ks << 5);
            uint32_t af[2][4], bh[2][4];
            ldmx4(af[0], sA + (a_base[0] ^ kx));
            ldmx4(af[1], sA + (a_base[1] ^ kx));
            ldmx4(bh[0], sB + (b_base[0] ^ kx));
            ldmx4(bh[1], sB + (b_base[1] ^ kx));
            #pragma unroll
            for (int mt = 0; mt < 2; ++mt) {
                mma16816(c[mt][0], af[mt], bh[0][0], bh[0][1]);
                mma16816(c[mt][1], af[mt], bh[0][2], bh[0][3]);
                mma16816(c[mt][2], af[mt], bh[1][0], bh[1][1]);
                mma16816(c[mt][3], af[mt], bh[1][2], bh[1][3]);
            }
        }

        if (lane == 0) mbar_arrive(sb + 64 + 8 * s);

        if (tid == 0 && ch + PREF < NKC) {
            const int cn = ch + PREF;
            if (cn >= NSTAGE)
                mbar_wait(sb + 64 + 8 * (cn & 3), ((cn >> 2) - 1) & 1);
            issue_chunk(cn);
        }
    }

    // ---- epilogue: gates c,o export accumulators to smem; gate-i warps combine ----
    __syncthreads();   // all mainloop smem reads done; safe to overwrite stages

    if (g > 0) {
        char* exg = exc + (g - 1) * (64 * EXROW);
        #pragma unroll
        for (int mt = 0; mt < 2; ++mt)
            #pragma unroll
            for (int half = 0; half < 2; ++half) {
                int mrow = (wm << 5) + (mt << 4) + (lane >> 2) + half * 8;
                char* rowp = exg + mrow * EXROW + (((wn << 5) + ((lane & 3) << 1)) << 2);
                #pragma unroll
                for (int nq = 0; nq < 4; ++nq) {
                    float2 v = make_float2(c[mt][nq][half * 2], c[mt][nq][half * 2 + 1]);
                    *(float2*)(rowp + (nq << 5)) = v;   // nq*8 floats = 32B
                }
            }
    }
    __syncthreads();

    if (g == 0) {
        const int ncb = n0 + (wn << 5) + ((lane & 3) << 1);
        float2 bi2[4], bc2[4], bo2[4];
        #pragma unroll
        for (int nq = 0; nq < 4; ++nq) {
            bi2[nq] = *(const float2*)(bxi + ncb + nq * 8);
            bc2[nq] = *(const float2*)(bxc + ncb + nq * 8);
            bo2[nq] = *(const float2*)(bxo + ncb + nq * 8);
        }
        #pragma unroll
        for (int mt = 0; mt < 2; ++mt) {
            #pragma unroll
            for (int half = 0; half < 2; ++half) {
                int mrow = (wm << 5) + (mt << 4) + (lane >> 2) + half * 8;
                char* rowp = exc + mrow * EXROW + (((wn << 5) + ((lane & 3) << 1)) << 2);
                size_t ob = (size_t)(m0 + mrow) * 512;
                #pragma unroll
                for (int nq = 0; nq < 4; ++nq) {
                    float2 cg = *(const float2*)(rowp + (nq << 5));
                    float2 og = *(const float2*)(rowp + 64 * EXROW + (nq << 5));
                    float hv[2], cv[2];
                    #pragma unroll
                    for (int e = 0; e < 2; ++e) {
                        float ip = c[mt][nq][half * 2 + e] + (e ? bi2[nq].y : bi2[nq].x);
                        float cp = (e ? cg.y : cg.x) + (e ? bc2[nq].y : bc2[nq].x);
                        float op = (e ? og.y : og.x) + (e ? bo2[nq].y : bo2[nq].x);
                        float ig = 1.0f / (1.0f + __expf(-ip));
                        float oo = 1.0f / (1.0f + __expf(-op));
                        float tc = 1.0f - 2.0f / (__expf(2.0f * cp) + 1.0f);
                        float cn = ig * tc;
                        float tn = 1.0f - 2.0f / (__expf(2.0f * cn) + 1.0f);
                        cv[e] = cn;
                        hv[e] = oo * tn;
                    }
                    *(float2*)(outh + ob + ncb + nq * 8) = *(float2*)hv;
                    *(float2*)(outc + ob + ncb + nq * 8) = *(float2*)cv;
                }
            }
        }
    }
}

// ---------------- launcher ----------------
extern "C" void kernel_launch(void* const* d_in, const int* in_sizes, int n_in,
                              void* d_out, int out_size) {
    // 0:x 1:h 2:c_prev 3:Wxi 4:bxi 5:Whi 6:Wxf 7:bxf 8:Whf 9:Wxc 10:bxc 11:Whc 12:Wxo 13:bxo 14:Who
    const float* x   = (const float*)d_in[0];
    const float* h   = (const float*)d_in[1];
    const float* Wxi = (const float*)d_in[3];
    const float* bxi = (const float*)d_in[4];
    const float* Whi = (const float*)d_in[5];
    const float* Wxc = (const float*)d_in[9];
    const float* bxc = (const float*)d_in[10];
    const float* Whc = (const float*)d_in[11];
    const float* Wxo = (const float*)d_in[12];
    const float* bxo = (const float*)d_in[13];
    const float* Who = (const float*)d_in[14];

    float* outh = (float*)d_out;
    float* outc = outh + (size_t)M_SZ * H_SZ;

    const int smem = 1024 + NSTAGE * (int)STAGE_BYTES + 4096;  // ctrl + stages (+ exchange slack)
    cudaFuncSetAttribute(lstm_gemm, cudaFuncAttributeMaxDynamicSharedMemorySize, smem);

    prep_a<<<16384, 256>>>(x, h);
    prep_b<<<dim3(48, 32), dim3(32, 8)>>>(Wxi, Whi, Wxc, Whc, Wxo, Who);
    dummy_k<<<1, 32>>>();
    lstm_gemm<<<dim3(8, 512), 384, smem>>>(bxi, bxc, bxo, outh, outc);
}

// round 14
// speedup vs baseline: 1.1123x; 1.1123x over previous
#include <cuda_runtime.h>
#include <cuda_fp16.h>
#include <cstdint>

// ---------------- problem constants ----------------
#define M_SZ 32768
#define H_SZ 512
#define K_SZ 1024
#define NKC  32              // k32 chunks
#define NSTAGE 4
#define STAGE_BYTES 20480u   // A 8KB + 3 x B 4KB
#define PREF 3

#define SWZ64(x) ((uint32_t)(x) ^ ((((uint32_t)(x)) >> 3) & 0x30))

// A blocks: [m>>7][kc] 8KB  (128 rows x 64B, SW64 pre-swizzled)
// B blocks: [(kc*3+g)*8 + n>>6] 4KB (64 rows x 64B, SW64 pre-swizzled)
__device__ __align__(128) unsigned char g_A[(size_t)M_SZ * 2048];          // 64MB
__device__ __align__(128) unsigned char g_B[(size_t)3 * H_SZ * 2048];      // 3MB

// ---------------- helpers ----------------
__device__ __forceinline__ uint32_t smem_u32(const void* p) {
    uint32_t a;
    asm("{ .reg .u64 t; cvta.to.shared.u64 t, %1; cvt.u32.u64 %0, t; }" : "=r"(a) : "l"(p));
    return a;
}
__device__ __forceinline__ void ldmx4(uint32_t* r, uint32_t a) {
    asm volatile("ldmatrix.sync.aligned.m8n8.x4.shared.b16 {%0,%1,%2,%3}, [%4];"
        : "=r"(r[0]), "=r"(r[1]), "=r"(r[2]), "=r"(r[3]) : "r"(a));
}
__device__ __forceinline__ void mma16816(float* c, const uint32_t* a, uint32_t b0, uint32_t b1) {
    asm volatile("mma.sync.aligned.m16n8k16.row.col.f32.f16.f16.f32 "
        "{%0,%1,%2,%3}, {%4,%5,%6,%7}, {%8,%9}, {%0,%1,%2,%3};"
        : "+f"(c[0]), "+f"(c[1]), "+f"(c[2]), "+f"(c[3])
        : "r"(a[0]), "r"(a[1]), "r"(a[2]), "r"(a[3]), "r"(b0), "r"(b1));
}
__device__ __forceinline__ void mbar_init(uint32_t a, uint32_t cnt) {
    asm volatile("mbarrier.init.shared.b64 [%0], %1;" :: "r"(a), "r"(cnt) : "memory");
}
__device__ __forceinline__ void mbar_expect_tx(uint32_t a, uint32_t tx) {
    asm volatile("mbarrier.arrive.expect_tx.shared.b64 _, [%0], %1;" :: "r"(a), "r"(tx) : "memory");
}
__device__ __forceinline__ void mbar_arrive(uint32_t a) {
    asm volatile("mbarrier.arrive.shared.b64 _, [%0];" :: "r"(a) : "memory");
}
__device__ __forceinline__ void mbar_wait(uint32_t a, uint32_t parity) {
    asm volatile(
        "{\n\t.reg .pred P;\n\t"
        "WL%=:\n\t"
        "mbarrier.try_wait.parity.acquire.cta.shared::cta.b64 P, [%0], %1, 0x989680;\n\t"
        "@P bra WD%=;\n\t"
        "bra WL%=;\n\t"
        "WD%=:\n\t}"
        :: "r"(a), "r"(parity) : "memory");
}
__device__ __forceinline__ void bulk_g2s(uint32_t dst, const void* src, uint32_t bytes, uint32_t mbar) {
    asm volatile(
        "cp.async.bulk.shared::cluster.global.mbarrier::complete_tx::bytes [%0], [%1], %2, [%3];"
        :: "r"(dst), "l"(src), "r"(bytes), "r"(mbar) : "memory");
}

// ---------------- dummy (shifts ncu capture window onto lstm_gemm) ----------------
__global__ void dummy_k() {}

// ---------------- prep A: fp32 -> fp16, 128m x k32 blocks, SW64 pre-swizzled ----------------
__global__ __launch_bounds__(256)
void prep_a(const float* __restrict__ x, const float* __restrict__ h) {
    int gid = blockIdx.x * 256 + threadIdx.x;      // 8 elems per thread
    int m = gid >> 7;
    int k8 = (gid & 127) << 3;
    const float* s = (k8 < 512) ? (x + (size_t)m * 512 + k8)
                                : (h + (size_t)m * 512 + (k8 - 512));
    float4 v0 = ((const float4*)s)[0];
    float4 v1 = ((const float4*)s)[1];
    __half hh[8];
    hh[0] = __float2half_rn(v0.x); hh[1] = __float2half_rn(v0.y);
    hh[2] = __float2half_rn(v0.z); hh[3] = __float2half_rn(v0.w);
    hh[4] = __float2half_rn(v1.x); hh[5] = __float2half_rn(v1.y);
    hh[6] = __float2half_rn(v1.z); hh[7] = __float2half_rn(v1.w);
    size_t blk = ((size_t)(m >> 7) * NKC + (k8 >> 5)) * 8192;
    uint32_t ob = SWZ64(((m & 127) << 6) + ((k8 & 31) << 1));
    *(uint4*)(g_A + blk + ob) = *(uint4*)hh;
}

// ---------------- prep B: transpose + fp16, 4KB 64n-blocks, SW64 pre-swizzled ----------------
__global__ void prep_b(const float* __restrict__ Wxi, const float* __restrict__ Whi,
                       const float* __restrict__ Wxc, const float* __restrict__ Whc,
                       const float* __restrict__ Wxo, const float* __restrict__ Who) {
    __shared__ float tile[32][33];
    int n0 = blockIdx.x * 32;       // 0..1535 (gate-major n)
    int k0 = blockIdx.y * 32;       // 0..1023
    int g = n0 >> 9;
    int nc0 = n0 & 511;
    const float* Wx = (g == 0) ? Wxi : ((g == 1) ? Wxc : Wxo);
    const float* Wh = (g == 0) ? Whi : ((g == 1) ? Whc : Who);
    int tx = threadIdx.x, ty = threadIdx.y;   // 32 x 8
    #pragma unroll
    for (int r = ty; r < 32; r += 8) {
        int k = k0 + r;
        const float* W = (k < 512) ? (Wx + (size_t)k * 512) : (Wh + (size_t)(k - 512) * 512);
        tile[r][tx] = W[nc0 + tx];
    }
    __syncthreads();
    #pragma unroll
    for (int r = ty; r < 32; r += 8) {
        float v = tile[tx][r];                 // W[k0+tx][n0+r]
        int n = nc0 + r;                       // gate-local 0..511
        int k = k0 + tx;
        size_t blk = ((size_t)((k >> 5) * 3 + g) * 8 + (n >> 6)) * 4096;
        uint32_t ob = SWZ64(((n & 63) << 6) + ((k & 31) << 1));
        *(__half*)(g_B + blk + ob) = __float2half_rn(v);
    }
}

// ---------------- fused GEMM + epilogue ----------------
// CTA 128m x 64n x 3 gates; 256 threads = 8 warps (2m x 4n), warp 64m x 16n per gate.
// 2 CTAs/SM (128 regs, ~81KB smem). k32 chunks, 4 stages, bulk-copy, no mainloop syncs.
__global__ __launch_bounds__(256, 2)
void lstm_gemm(const float* __restrict__ bxi, const float* __restrict__ bxc,
               const float* __restrict__ bxo,
               float* __restrict__ outh, float* __restrict__ outc) {
    extern __shared__ char dsm[];
    const uint32_t sb = (smem_u32(dsm) + 1023) & ~1023u;   // full[4]@0, empty[4]@64
    const uint32_t sd = sb + 1024;                          // stage data (4 x 20KB)

    const int tid  = threadIdx.x;
    const int lane = tid & 31;
    const int wid  = tid >> 5;
    const int wm   = wid >> 2;       // 0..1 -> m offset 64*wm
    const int wn   = wid & 3;        // 0..3 -> n offset 16*wn
    const int m0   = blockIdx.y << 7;
    const int mb   = blockIdx.y;     // 128m block
    const int nb   = blockIdx.x;     // 64n block (0..7)

    if (tid == 0) {
        #pragma unroll
        for (int s = 0; s < NSTAGE; ++s) {
            mbar_init(sb + 8 * s, 1);        // full: tx-based
            mbar_init(sb + 64 + 8 * s, 8);   // empty: 8 warp arrivals
        }
        asm volatile("fence.proxy.async.shared::cta;" ::: "memory");
    }
    __syncthreads();

    auto issue_chunk = [&](int c) {
        const int s = c & 3;
        const uint32_t mbar = sb + 8 * s;
        const uint32_t dst = sd + (uint32_t)s * STAGE_BYTES;
        mbar_expect_tx(mbar, STAGE_BYTES);
        bulk_g2s(dst, g_A + ((size_t)mb * NKC + c) * 8192, 8192u, mbar);
        #pragma unroll
        for (int gg = 0; gg < 3; ++gg)
            bulk_g2s(dst + 8192u + 4096u * gg,
                     g_B + ((size_t)((c * 3 + gg) * 8) + nb) * 4096, 4096u, mbar);
    };

    if (tid == 0) {
        issue_chunk(0);
        issue_chunk(1);
        issue_chunk(2);
    }

    // A ldmatrix bases (SW64, 64B rows); per-ks XOR 32
    uint32_t a_base[4];
    #pragma unroll
    for (int mt = 0; mt < 4; ++mt) {
        int row = (wm << 6) + (mt << 4) + (lane & 15);
        int ro  = row * 64 + ((lane >> 4) << 4);
        a_base[mt] = SWZ64(ro);
    }
    // B ldmatrix base: 16 rows (warp's n16) x k16
    uint32_t b_base;
    {
        int rr = (wn << 4) + (lane & 7) + (((lane >> 4) & 1) << 3);
        int ro = rr * 64 + (((lane >> 3) & 1) << 4);
        b_base = SWZ64(ro);
    }

    float c[3][4][2][4];   // gate, mt(4), nt(2), e -> 96 regs
    #pragma unroll
    for (int g = 0; g < 3; ++g)
        #pragma unroll
        for (int mt = 0; mt < 4; ++mt)
            #pragma unroll
            for (int nt = 0; nt < 2; ++nt)
                #pragma unroll
                for (int e = 0; e < 4; ++e) c[g][mt][nt][e] = 0.0f;

    for (int ch = 0; ch < NKC; ++ch) {
        const int s = ch & 3;
        mbar_wait(sb + 8 * s, (ch >> 2) & 1);

        const uint32_t sA = sd + (uint32_t)s * STAGE_BYTES;
        const uint32_t sB = sA + 8192u;

        #pragma unroll
        for (int ks = 0; ks < 2; ++ks) {
            const uint32_t kx = (uint32_t)(ks << 5);
            uint32_t af[4][4];
            #pragma unroll
            for (int mt = 0; mt < 4; ++mt)
                ldmx4(af[mt], sA + (a_base[mt] ^ kx));
            #pragma unroll
            for (int g = 0; g < 3; ++g) {
                uint32_t bh[4];
                ldmx4(bh, sB + 4096u * (uint32_t)g + (b_base ^ kx));
                #pragma unroll
                for (int mt = 0; mt < 4; ++mt) {
                    mma16816(c[g][mt][0], af[mt], bh[0], bh[1]);
                    mma16816(c[g][mt][1], af[mt], bh[2], bh[3]);
                }
            }
        }

        if (lane == 0) mbar_arrive(sb + 64 + 8 * s);

        if (tid == 0 && ch + PREF < NKC) {
            const int cn = ch + PREF;
            if (cn >= NSTAGE)
                mbar_wait(sb + 64 + 8 * (cn & 3), ((cn >> 2) - 1) & 1);
            issue_chunk(cn);
        }
    }

    // ---- fused epilogue ----
    const int ncb = (nb << 6) + (wn << 4) + ((lane & 3) << 1);
    float2 bi2[2], bc2[2], bo2[2];
    #pragma unroll
    for (int nt = 0; nt < 2; ++nt) {
        bi2[nt] = *(const float2*)(bxi + ncb + nt * 8);
        bc2[nt] = *(const float2*)(bxc + ncb + nt * 8);
        bo2[nt] = *(const float2*)(bxo + ncb + nt * 8);
    }

    #pragma unroll
    for (int mt = 0; mt < 4; ++mt) {
        #pragma unroll
        for (int half = 0; half < 2; ++half) {
            int m = m0 + (wm << 6) + (mt << 4) + (lane >> 2) + half * 8;
            size_t ob = (size_t)m * 512;
            #pragma unroll
            for (int nt = 0; nt < 2; ++nt) {
                float hv[2], cv[2];
                #pragma unroll
                for (int e = 0; e < 2; ++e) {
                    int idx = half * 2 + e;
                    float ip = c[0][mt][nt][idx] + (e ? bi2[nt].y : bi2[nt].x);
                    float cp = c[1][mt][nt][idx] + (e ? bc2[nt].y : bc2[nt].x);
                    float op = c[2][mt][nt][idx] + (e ? bo2[nt].y : bo2[nt].x);
                    float ig = 1.0f / (1.0f + __expf(-ip));
                    float og = 1.0f / (1.0f + __expf(-op));
                    float tc = 1.0f - 2.0f / (__expf(2.0f * cp) + 1.0f);
                    float cn = ig * tc;
                    float tn = 1.0f - 2.0f / (__expf(2.0f * cn) + 1.0f);
                    cv[e] = cn;
                    hv[e] = og * tn;
                }
                *(float2*)(outh + ob + ncb + nt * 8) = *(float2*)hv;
                *(float2*)(outc + ob + ncb + nt * 8) = *(float2*)cv;
            }
        }
    }
}

// ---------------- launcher ----------------
extern "C" void kernel_launch(void* const* d_in, const int* in_sizes, int n_in,
                              void* d_out, int out_size) {
    // 0:x 1:h 2:c_prev 3:Wxi 4:bxi 5:Whi 6:Wxf 7:bxf 8:Whf 9:Wxc 10:bxc 11:Whc 12:Wxo 13:bxo 14:Who
    const float* x   = (const float*)d_in[0];
    const float* h   = (const float*)d_in[1];
    const float* Wxi = (const float*)d_in[3];
    const float* bxi = (const float*)d_in[4];
    const float* Whi = (const float*)d_in[5];
    const float* Wxc = (const float*)d_in[9];
    const float* bxc = (const float*)d_in[10];
    const float* Whc = (const float*)d_in[11];
    const float* Wxo = (const float*)d_in[12];
    const float* bxo = (const float*)d_in[13];
    const float* Who = (const float*)d_in[14];

    float* outh = (float*)d_out;
    float* outc = outh + (size_t)M_SZ * H_SZ;

    const int smem = 1024 + NSTAGE * (int)STAGE_BYTES;   // 82944 -> 2 CTAs/SM
    cudaFuncSetAttribute(lstm_gemm, cudaFuncAttributeMaxDynamicSharedMemorySize, smem);

    prep_a<<<16384, 256>>>(x, h);
    prep_b<<<dim3(48, 32), dim3(32, 8)>>>(Wxi, Whi, Wxc, Whc, Wxo, Who);
    dummy_k<<<1, 32>>>();
    lstm_gemm<<<dim3(8, 256), 256, smem>>>(bxi, bxc, bxo, outh, outc);
}

// round 15
// speedup vs baseline: 1.8594x; 1.6717x over previous
#include <cuda_runtime.h>
#include <cuda_fp16.h>
#include <cstdint>

// ---------------- problem constants ----------------
#define M_SZ 32768
#define H_SZ 512
#define K_SZ 1024
#define NKC  32              // k32 chunks
#define NSTAGE 4
#define STAGE_BYTES 28672u   // A 4KB + 3 x B 8KB
#define PREF 3

#define SWZ64(x) ((uint32_t)(x) ^ ((((uint32_t)(x)) >> 3) & 0x30))

// A blocks: [m>>6][kc] 4KB  (64 rows x 64B, SW64 pre-swizzled)
// B blocks: [(kc*3+g)*4 + n>>7] 8KB (128 rows x 64B, SW64 pre-swizzled)
__device__ __align__(128) unsigned char g_A[(size_t)M_SZ * 2048];          // 64MB
__device__ __align__(128) unsigned char g_B[(size_t)3 * H_SZ * 2048];      // 3MB

// ---------------- helpers ----------------
__device__ __forceinline__ uint32_t smem_u32(const void* p) {
    uint32_t a;
    asm("{ .reg .u64 t; cvta.to.shared.u64 t, %1; cvt.u32.u64 %0, t; }" : "=r"(a) : "l"(p));
    return a;
}
__device__ __forceinline__ void ldmx4(uint32_t* r, uint32_t a) {
    asm volatile("ldmatrix.sync.aligned.m8n8.x4.shared.b16 {%0,%1,%2,%3}, [%4];"
        : "=r"(r[0]), "=r"(r[1]), "=r"(r[2]), "=r"(r[3]) : "r"(a));
}
__device__ __forceinline__ void mma16816(float* c, const uint32_t* a, uint32_t b0, uint32_t b1) {
    asm volatile("mma.sync.aligned.m16n8k16.row.col.f32.f16.f16.f32 "
        "{%0,%1,%2,%3}, {%4,%5,%6,%7}, {%8,%9}, {%0,%1,%2,%3};"
        : "+f"(c[0]), "+f"(c[1]), "+f"(c[2]), "+f"(c[3])
        : "r"(a[0]), "r"(a[1]), "r"(a[2]), "r"(a[3]), "r"(b0), "r"(b1));
}
__device__ __forceinline__ void mbar_init(uint32_t a, uint32_t cnt) {
    asm volatile("mbarrier.init.shared.b64 [%0], %1;" :: "r"(a), "r"(cnt) : "memory");
}
__device__ __forceinline__ void mbar_expect_tx(uint32_t a, uint32_t tx) {
    asm volatile("mbarrier.arrive.expect_tx.shared.b64 _, [%0], %1;" :: "r"(a), "r"(tx) : "memory");
}
__device__ __forceinline__ void mbar_arrive(uint32_t a) {
    asm volatile("mbarrier.arrive.shared.b64 _, [%0];" :: "r"(a) : "memory");
}
__device__ __forceinline__ void mbar_wait(uint32_t a, uint32_t parity) {
    asm volatile(
        "{\n\t.reg .pred P;\n\t"
        "WL%=:\n\t"
        "mbarrier.try_wait.parity.acquire.cta.shared::cta.b64 P, [%0], %1, 0x989680;\n\t"
        "@P bra WD%=;\n\t"
        "bra WL%=;\n\t"
        "WD%=:\n\t}"
        :: "r"(a), "r"(parity) : "memory");
}
__device__ __forceinline__ void bulk_g2s(uint32_t dst, const void* src, uint32_t bytes, uint32_t mbar) {
    asm volatile(
        "cp.async.bulk.shared::cluster.global.mbarrier::complete_tx::bytes [%0], [%1], %2, [%3];"
        :: "r"(dst), "l"(src), "r"(bytes), "r"(mbar) : "memory");
}

// ---------------- prep A: fp32 -> fp16, 64m x k32 blocks, pre-swizzled ----------------
__global__ __launch_bounds__(256)
void prep_a(const float* __restrict__ x, const float* __restrict__ h) {
    int gid = blockIdx.x * 256 + threadIdx.x;      // 8 elems per thread
    int m = gid >> 7;
    int k8 = (gid & 127) << 3;
    const float* s = (k8 < 512) ? (x + (size_t)m * 512 + k8)
                                : (h + (size_t)m * 512 + (k8 - 512));
    float4 v0 = ((const float4*)s)[0];
    float4 v1 = ((const float4*)s)[1];
    __half hh[8];
    hh[0] = __float2half_rn(v0.x); hh[1] = __float2half_rn(v0.y);
    hh[2] = __float2half_rn(v0.z); hh[3] = __float2half_rn(v0.w);
    hh[4] = __float2half_rn(v1.x); hh[5] = __float2half_rn(v1.y);
    hh[6] = __float2half_rn(v1.z); hh[7] = __float2half_rn(v1.w);
    size_t blk = ((size_t)(m >> 6) * NKC + (k8 >> 5)) * 4096;
    uint32_t ob = SWZ64(((m & 63) << 6) + ((k8 & 31) << 1));
    *(uint4*)(g_A + blk + ob) = *(uint4*)hh;
}

// ---------------- prep B: transpose + fp16, 8KB blocks, pre-swizzled ----------------
__global__ void prep_b(const float* __restrict__ Wxi, const float* __restrict__ Whi,
                       const float* __restrict__ Wxc, const float* __restrict__ Whc,
                       const float* __restrict__ Wxo, const float* __restrict__ Who) {
    __shared__ float tile[32][33];
    int n0 = blockIdx.x * 32;       // 0..1535 (gate-major n)
    int k0 = blockIdx.y * 32;       // 0..1023
    int g = n0 >> 9;
    int nc0 = n0 & 511;
    const float* Wx = (g == 0) ? Wxi : ((g == 1) ? Wxc : Wxo);
    const float* Wh = (g == 0) ? Whi : ((g == 1) ? Whc : Who);
    int tx = threadIdx.x, ty = threadIdx.y;   // 32 x 8
    #pragma unroll
    for (int r = ty; r < 32; r += 8) {
        int k = k0 + r;
        const float* W = (k < 512) ? (Wx + (size_t)k * 512) : (Wh + (size_t)(k - 512) * 512);
        tile[r][tx] = W[nc0 + tx];
    }
    __syncthreads();
    #pragma unroll
    for (int r = ty; r < 32; r += 8) {
        float v = tile[tx][r];                 // W[k0+tx][n0+r]
        int n = nc0 + r;                       // gate-local 0..511
        int k = k0 + tx;
        size_t blk = ((size_t)((k >> 5) * 3 + g) * 4 + (n >> 7)) * 8192;
        uint32_t ob = SWZ64(((n & 127) << 6) + ((k & 31) << 1));
        *(__half*)(g_B + blk + ob) = __float2half_rn(v);
    }
}

// ---------------- fused GEMM + epilogue ----------------
// CTA 64m x 128n x 3 gates; 256 threads = 8 warps (2m x 4n), warp 32x32/gate.
// 2 CTAs/SM. k32 stages, 4-deep, bulk-copy, no syncthreads in mainloop.
// ks-stagger: odd warps process k16 halves in order (1,0) to decorrelate LDSM bursts.
__global__ __launch_bounds__(256, 2)
void lstm_gemm(const float* __restrict__ bxi, const float* __restrict__ bxc,
               const float* __restrict__ bxo,
               float* __restrict__ outh, float* __restrict__ outc) {
    extern __shared__ char dsm[];
    const uint32_t sb = (smem_u32(dsm) + 1023) & ~1023u;   // full[4]@0, empty[4]@64
    const uint32_t sd = sb + 1024;                          // stage data

    const int tid  = threadIdx.x;
    const int lane = tid & 31;
    const int wid  = tid >> 5;
    const int wm   = wid >> 2;       // 0..1 -> m offset 32*wm
    const int wn   = wid & 3;        // 0..3 -> n offset 32*wn
    const int ksx  = wid & 1;        // ks processing order stagger
    const int m0   = blockIdx.y << 6;
    const int n0   = blockIdx.x << 7;
    const int mb   = blockIdx.y;     // 64-row m-block index
    const int nb   = blockIdx.x;

    if (tid == 0) {
        #pragma unroll
        for (int s = 0; s < NSTAGE; ++s) {
            mbar_init(sb + 8 * s, 1);        // full: tx-based
            mbar_init(sb + 64 + 8 * s, 8);   // empty: 8 warp arrivals
        }
        asm volatile("fence.proxy.async.shared::cta;" ::: "memory");
    }
    __syncthreads();

    auto issue_chunk = [&](int c) {
        const int s = c % NSTAGE;
        const uint32_t mbar = sb + 8 * s;
        const uint32_t dst = sd + (uint32_t)s * STAGE_BYTES;
        mbar_expect_tx(mbar, STAGE_BYTES);
        bulk_g2s(dst, g_A + ((size_t)mb * NKC + c) * 4096, 4096u, mbar);
        #pragma unroll
        for (int g = 0; g < 3; ++g)
            bulk_g2s(dst + 4096u + 8192u * g,
                     g_B + ((size_t)((c * 3 + g) * 4) + nb) * 8192, 8192u, mbar);
    };

    if (tid == 0) {
        issue_chunk(0);
        issue_chunk(1);
        issue_chunk(2);
    }

    // ldmatrix bases (SW64, 64B rows); per-ks XOR 32
    uint32_t a_base[2];
    #pragma unroll
    for (int mt = 0; mt < 2; ++mt) {
        int row = (wm << 5) + (mt << 4) + (lane & 15);
        int ro  = row * 64 + ((lane >> 4) << 4);
        a_base[mt] = SWZ64(ro);
    }
    uint32_t b_base[2];
    #pragma unroll
    for (int ng = 0; ng < 2; ++ng) {
        int rr = (wn << 5) + (ng << 4) + (lane & 7) + (((lane >> 4) & 1) << 3);
        int ro = rr * 64 + (((lane >> 3) & 1) << 4);
        b_base[ng] = SWZ64(ro);
    }

    float c[3][2][4][4];   // gate, mt, nt, e -> 96 regs
    #pragma unroll
    for (int g = 0; g < 3; ++g)
        #pragma unroll
        for (int mt = 0; mt < 2; ++mt)
            #pragma unroll
            for (int nt = 0; nt < 4; ++nt)
                #pragma unroll
                for (int e = 0; e < 4; ++e) c[g][mt][nt][e] = 0.0f;

    for (int ch = 0; ch < NKC; ++ch) {
        const int s = ch % NSTAGE;
        mbar_wait(sb + 8 * s, (ch / NSTAGE) & 1);

        const uint32_t sA = sd + (uint32_t)s * STAGE_BYTES;
        const uint32_t sB = sA + 4096u;

        #pragma unroll
        for (int kss = 0; kss < 2; ++kss) {
            const int ks = kss ^ ksx;                 // stagger across warps
            const uint32_t kx = (uint32_t)(ks << 5);
            uint32_t af[2][4];
            ldmx4(af[0], sA + (a_base[0] ^ kx));
            ldmx4(af[1], sA + (a_base[1] ^ kx));
            #pragma unroll
            for (int g = 0; g < 3; ++g) {
                const uint32_t bb = sB + (uint32_t)(g << 13);
                #pragma unroll
                for (int ng = 0; ng < 2; ++ng) {
                    uint32_t bh[4];
                    ldmx4(bh, bb + (b_base[ng] ^ kx));
                    #pragma unroll
                    for (int mt = 0; mt < 2; ++mt) {
                        mma16816(c[g][mt][2*ng+0], af[mt], bh[0], bh[1]);
                        mma16816(c[g][mt][2*ng+1], af[mt], bh[2], bh[3]);
                    }
                }
            }
        }

        if (lane == 0) mbar_arrive(sb + 64 + 8 * s);

        if (tid == 0 && ch + PREF < NKC) {
            const int cn = ch + PREF;
            if (cn >= NSTAGE)
                mbar_wait(sb + 64 + 8 * (cn % NSTAGE), ((cn / NSTAGE) - 1) & 1);
            issue_chunk(cn);
        }
    }

    // ---- fused epilogue ----
    const int ncb = n0 + (wn << 5) + ((lane & 3) << 1);
    float2 bi2[4], bc2[4], bo2[4];
    #pragma unroll
    for (int nt = 0; nt < 4; ++nt) {
        bi2[nt] = *(const float2*)(bxi + ncb + nt * 8);
        bc2[nt] = *(const float2*)(bxc + ncb + nt * 8);
        bo2[nt] = *(const float2*)(bxo + ncb + nt * 8);
    }

    #pragma unroll
    for (int mt = 0; mt < 2; ++mt) {
        #pragma unroll
        for (int half = 0; half < 2; ++half) {
            int m = m0 + (wm << 5) + (mt << 4) + (lane >> 2) + half * 8;
            size_t ob = (size_t)m * 512;
            #pragma unroll
            for (int nt = 0; nt < 4; ++nt) {
                float hv[2], cv[2];
                #pragma unroll
                for (int e = 0; e < 2; ++e) {
                    int idx = half * 2 + e;
                    float ip = c[0][mt][nt][idx] + (e ? bi2[nt].y : bi2[nt].x);
                    float cp = c[1][mt][nt][idx] + (e ? bc2[nt].y : bc2[nt].x);
                    float op = c[2][mt][nt][idx] + (e ? bo2[nt].y : bo2[nt].x);
                    float ig = 1.0f / (1.0f + __expf(-ip));
                    float og = 1.0f / (1.0f + __expf(-op));
                    float tc = 1.0f - 2.0f / (__expf(2.0f * cp) + 1.0f);
                    float cn = ig * tc;
                    float tn = 1.0f - 2.0f / (__expf(2.0f * cn) + 1.0f);
                    cv[e] = cn;
                    hv[e] = og * tn;
                }
                *(float2*)(outh + ob + ncb + nt * 8) = *(float2*)hv;
                *(float2*)(outc + ob + ncb + nt * 8) = *(float2*)cv;
            }
        }
    }
}

// ---------------- launcher ----------------
extern "C" void kernel_launch(void* const* d_in, const int* in_sizes, int n_in,
                              void* d_out, int out_size) {
    // 0:x 1:h 2:c_prev 3:Wxi 4:bxi 5:Whi 6:Wxf 7:bxf 8:Whf 9:Wxc 10:bxc 11:Whc 12:Wxo 13:bxo 14:Who
    const float* x   = (const float*)d_in[0];
    const float* h   = (const float*)d_in[1];
    const float* Wxi = (const float*)d_in[3];
    const float* bxi = (const float*)d_in[4];
    const float* Whi = (const float*)d_in[5];
    const float* Wxc = (const float*)d_in[9];
    const float* bxc = (const float*)d_in[10];
    const float* Whc = (const float*)d_in[11];
    const float* Wxo = (const float*)d_in[12];
    const float* bxo = (const float*)d_in[13];
    const float* Who = (const float*)d_in[14];

    float* outh = (float*)d_out;
    float* outc = outh + (size_t)M_SZ * H_SZ;

    const int smem = 1024 + NSTAGE * (int)STAGE_BYTES;   // 115712 -> 2 CTAs/SM
    cudaFuncSetAttribute(lstm_gemm, cudaFuncAttributeMaxDynamicSharedMemorySize, smem);

    prep_a<<<16384, 256>>>(x, h);
    prep_b<<<dim3(48, 32), dim3(32, 8)>>>(Wxi, Whi, Wxc, Whc, Wxo, Who);
    lstm_gemm<<<dim3(4, 512), 256, smem>>>(bxi, bxc, bxo, outh, outc);
}

// round 16
// speedup vs baseline: 2.0001x; 1.0756x over previous
#include <cuda_runtime.h>
#include <cuda_fp16.h>
#include <cstdint>

// ---------------- problem constants ----------------
#define M_SZ 32768
#define H_SZ 512
#define K_SZ 1024
#define NKC  32              // k32 chunks
#define NSTAGE 4
#define STAGE_BYTES 28672u   // A 4KB + 3 x B 8KB
#define PREF 3

#define SWZ64(x) ((uint32_t)(x) ^ ((((uint32_t)(x)) >> 3) & 0x30))

// A blocks: [m>>6][kc] 4KB  (64 rows x 64B, SW64 pre-swizzled)
// B blocks: [(kc*3+g)*4 + n>>7] 8KB (128 rows x 64B, SW64 pre-swizzled)
__device__ __align__(128) unsigned char g_A[(size_t)M_SZ * 2048];          // 64MB
__device__ __align__(128) unsigned char g_B[(size_t)3 * H_SZ * 2048];      // 3MB

// ---------------- helpers ----------------
__device__ __forceinline__ uint32_t smem_u32(const void* p) {
    uint32_t a;
    asm("{ .reg .u64 t; cvta.to.shared.u64 t, %1; cvt.u32.u64 %0, t; }" : "=r"(a) : "l"(p));
    return a;
}
__device__ __forceinline__ void ldmx4(uint32_t* r, uint32_t a) {
    asm volatile("ldmatrix.sync.aligned.m8n8.x4.shared.b16 {%0,%1,%2,%3}, [%4];"
        : "=r"(r[0]), "=r"(r[1]), "=r"(r[2]), "=r"(r[3]) : "r"(a));
}
__device__ __forceinline__ void mma16816(float* c, const uint32_t* a, uint32_t b0, uint32_t b1) {
    asm volatile("mma.sync.aligned.m16n8k16.row.col.f32.f16.f16.f32 "
        "{%0,%1,%2,%3}, {%4,%5,%6,%7}, {%8,%9}, {%0,%1,%2,%3};"
        : "+f"(c[0]), "+f"(c[1]), "+f"(c[2]), "+f"(c[3])
        : "r"(a[0]), "r"(a[1]), "r"(a[2]), "r"(a[3]), "r"(b0), "r"(b1));
}
__device__ __forceinline__ void mbar_init(uint32_t a, uint32_t cnt) {
    asm volatile("mbarrier.init.shared.b64 [%0], %1;" :: "r"(a), "r"(cnt) : "memory");
}
__device__ __forceinline__ void mbar_expect_tx(uint32_t a, uint32_t tx) {
    asm volatile("mbarrier.arrive.expect_tx.shared.b64 _, [%0], %1;" :: "r"(a), "r"(tx) : "memory");
}
__device__ __forceinline__ void mbar_arrive(uint32_t a) {
    asm volatile("mbarrier.arrive.shared.b64 _, [%0];" :: "r"(a) : "memory");
}
__device__ __forceinline__ void mbar_wait(uint32_t a, uint32_t parity) {
    asm volatile(
        "{\n\t.reg .pred P;\n\t"
        "WL%=:\n\t"
        "mbarrier.try_wait.parity.acquire.cta.shared::cta.b64 P, [%0], %1, 0x989680;\n\t"
        "@P bra WD%=;\n\t"
        "bra WL%=;\n\t"
        "WD%=:\n\t}"
        :: "r"(a), "r"(parity) : "memory");
}
__device__ __forceinline__ void bulk_g2s(uint32_t dst, const void* src, uint32_t bytes, uint32_t mbar) {
    asm volatile(
        "cp.async.bulk.shared::cluster.global.mbarrier::complete_tx::bytes [%0], [%1], %2, [%3];"
        :: "r"(dst), "l"(src), "r"(bytes), "r"(mbar) : "memory");
}

// ---------------- merged prep: A convert + B transpose/convert ----------------
// blocks [0, 8192): prep_a (each thread: 16 elems, 2 rows' worth)
// blocks [8192, 8192+1536): prep_b tile transpose
__global__ __launch_bounds__(256)
void prep_ab(const float* __restrict__ x, const float* __restrict__ h,
             const float* __restrict__ Wxi, const float* __restrict__ Whi,
             const float* __restrict__ Wxc, const float* __restrict__ Whc,
             const float* __restrict__ Wxo, const float* __restrict__ Who) {
    if (blockIdx.x < 8192) {
        // ---- prep A: fp32 -> fp16, 64m x k32 blocks, SW64 pre-swizzled ----
        int gid = blockIdx.x * 256 + threadIdx.x;      // 16 elems per thread
        #pragma unroll
        for (int half = 0; half < 2; ++half) {
            int eid = gid * 2 + half;                  // 8-elem unit id
            int m = eid >> 7;
            int k8 = (eid & 127) << 3;
            const float* s = (k8 < 512) ? (x + (size_t)m * 512 + k8)
                                        : (h + (size_t)m * 512 + (k8 - 512));
            float4 v0 = ((const float4*)s)[0];
            float4 v1 = ((const float4*)s)[1];
            __half hh[8];
            hh[0] = __float2half_rn(v0.x); hh[1] = __float2half_rn(v0.y);
            hh[2] = __float2half_rn(v0.z); hh[3] = __float2half_rn(v0.w);
            hh[4] = __float2half_rn(v1.x); hh[5] = __float2half_rn(v1.y);
            hh[6] = __float2half_rn(v1.z); hh[7] = __float2half_rn(v1.w);
            size_t blk = ((size_t)(m >> 6) * NKC + (k8 >> 5)) * 4096;
            uint32_t ob = SWZ64(((m & 63) << 6) + ((k8 & 31) << 1));
            *(uint4*)(g_A + blk + ob) = *(uint4*)hh;
        }
    } else {
        // ---- prep B: transpose + fp16, 8KB blocks, SW64 pre-swizzled ----
        __shared__ float tile[32][33];
        int bid = blockIdx.x - 8192;                   // 0..1535
        int n0 = (bid % 48) * 32;                      // 0..1535 (gate-major n)
        int k0 = (bid / 48) * 32;                      // 0..1023
        int g = n0 >> 9;
        int nc0 = n0 & 511;
        const float* Wx = (g == 0) ? Wxi : ((g == 1) ? Wxc : Wxo);
        const float* Wh = (g == 0) ? Whi : ((g == 1) ? Whc : Who);
        int tx = threadIdx.x & 31, ty = threadIdx.x >> 5;   // 32 x 8
        #pragma unroll
        for (int r = ty; r < 32; r += 8) {
            int k = k0 + r;
            const float* W = (k < 512) ? (Wx + (size_t)k * 512) : (Wh + (size_t)(k - 512) * 512);
            tile[r][tx] = W[nc0 + tx];
        }
        __syncthreads();
        #pragma unroll
        for (int r = ty; r < 32; r += 8) {
            float v = tile[tx][r];                 // W[k0+tx][n0+r]
            int n = nc0 + r;                       // gate-local 0..511
            int k = k0 + tx;
            size_t blk = ((size_t)((k >> 5) * 3 + g) * 4 + (n >> 7)) * 8192;
            uint32_t ob = SWZ64(((n & 127) << 6) + ((k & 31) << 1));
            *(__half*)(g_B + blk + ob) = __float2half_rn(v);
        }
    }
}

// ---------------- fused GEMM + epilogue ----------------
// CTA 64m x 128n x 3 gates; 256 threads = 8 warps (2m x 4n), warp 32x32/gate.
// 2 CTAs/SM. k32 stages, 4-deep, bulk-copy, no syncthreads in mainloop.
// ks-stagger across warps; producer role rotates: chunk ch issued by warp ch%8.
__global__ __launch_bounds__(256, 2)
void lstm_gemm(const float* __restrict__ bxi, const float* __restrict__ bxc,
               const float* __restrict__ bxo,
               float* __restrict__ outh, float* __restrict__ outc) {
    extern __shared__ char dsm[];
    const uint32_t sb = (smem_u32(dsm) + 1023) & ~1023u;   // full[4]@0, empty[4]@64
    const uint32_t sd = sb + 1024;                          // stage data

    const int tid  = threadIdx.x;
    const int lane = tid & 31;
    const int wid  = tid >> 5;
    const int wm   = wid >> 2;       // 0..1 -> m offset 32*wm
    const int wn   = wid & 3;        // 0..3 -> n offset 32*wn
    const int ksx  = wid & 1;        // ks processing order stagger
    const int m0   = blockIdx.y << 6;
    const int n0   = blockIdx.x << 7;
    const int mb   = blockIdx.y;     // 64-row m-block index
    const int nb   = blockIdx.x;

    if (tid == 0) {
        #pragma unroll
        for (int s = 0; s < NSTAGE; ++s) {
            mbar_init(sb + 8 * s, 1);        // full: tx-based
            mbar_init(sb + 64 + 8 * s, 8);   // empty: 8 warp arrivals
        }
        asm volatile("fence.proxy.async.shared::cta;" ::: "memory");
    }
    __syncthreads();

    auto issue_chunk = [&](int c) {
        const int s = c % NSTAGE;
        const uint32_t mbar = sb + 8 * s;
        const uint32_t dst = sd + (uint32_t)s * STAGE_BYTES;
        mbar_expect_tx(mbar, STAGE_BYTES);
        bulk_g2s(dst, g_A + ((size_t)mb * NKC + c) * 4096, 4096u, mbar);
        #pragma unroll
        for (int g = 0; g < 3; ++g)
            bulk_g2s(dst + 4096u + 8192u * g,
                     g_B + ((size_t)((c * 3 + g) * 4) + nb) * 8192, 8192u, mbar);
    };

    if (tid == 0) {
        issue_chunk(0);
        issue_chunk(1);
        issue_chunk(2);
    }

    // ldmatrix bases (SW64, 64B rows); per-ks XOR 32
    uint32_t a_base[2];
    #pragma unroll
    for (int mt = 0; mt < 2; ++mt) {
        int row = (wm << 5) + (mt << 4) + (lane & 15);
        int ro  = row * 64 + ((lane >> 4) << 4);
        a_base[mt] = SWZ64(ro);
    }
    uint32_t b_base[2];
    #pragma unroll
    for (int ng = 0; ng < 2; ++ng) {
        int rr = (wn << 5) + (ng << 4) + (lane & 7) + (((lane >> 4) & 1) << 3);
        int ro = rr * 64 + (((lane >> 3) & 1) << 4);
        b_base[ng] = SWZ64(ro);
    }

    float c[3][2][4][4];   // gate, mt, nt, e -> 96 regs
    #pragma unroll
    for (int g = 0; g < 3; ++g)
        #pragma unroll
        for (int mt = 0; mt < 2; ++mt)
            #pragma unroll
            for (int nt = 0; nt < 4; ++nt)
                #pragma unroll
                for (int e = 0; e < 4; ++e) c[g][mt][nt][e] = 0.0f;

    for (int ch = 0; ch < NKC; ++ch) {
        const int s = ch % NSTAGE;
        mbar_wait(sb + 8 * s, (ch / NSTAGE) & 1);

        const uint32_t sA = sd + (uint32_t)s * STAGE_BYTES;
        const uint32_t sB = sA + 4096u;

        #pragma unroll
        for (int kss = 0; kss < 2; ++kss) {
            const int ks = kss ^ ksx;                 // stagger across warps
            const uint32_t kx = (uint32_t)(ks << 5);
            uint32_t af[2][4];
            ldmx4(af[0], sA + (a_base[0] ^ kx));
            ldmx4(af[1], sA + (a_base[1] ^ kx));
            #pragma unroll
            for (int g = 0; g < 3; ++g) {
                const uint32_t bb = sB + (uint32_t)(g << 13);
                #pragma unroll
                for (int ng = 0; ng < 2; ++ng) {
                    uint32_t bh[4];
                    ldmx4(bh, bb + (b_base[ng] ^ kx));
                    #pragma unroll
                    for (int mt = 0; mt < 2; ++mt) {
                        mma16816(c[g][mt][2*ng+0], af[mt], bh[0], bh[1]);
                        mma16816(c[g][mt][2*ng+1], af[mt], bh[2], bh[3]);
                    }
                }
            }
        }

        if (lane == 0) mbar_arrive(sb + 64 + 8 * s);

        // producer rotation: chunk cn issued by warp cn%8 (lane 0)
        const int cn = ch + PREF;
        if (cn < NKC && wid == (cn & 7) && lane == 0) {
            if (cn >= NSTAGE)
                mbar_wait(sb + 64 + 8 * (cn % NSTAGE), ((cn / NSTAGE) - 1) & 1);
            issue_chunk(cn);
        }
    }

    // ---- fused epilogue ----
    const int ncb = n0 + (wn << 5) + ((lane & 3) << 1);
    float2 bi2[4], bc2[4], bo2[4];
    #pragma unroll
    for (int nt = 0; nt < 4; ++nt) {
        bi2[nt] = *(const float2*)(bxi + ncb + nt * 8);
        bc2[nt] = *(const float2*)(bxc + ncb + nt * 8);
        bo2[nt] = *(const float2*)(bxo + ncb + nt * 8);
    }

    #pragma unroll
    for (int mt = 0; mt < 2; ++mt) {
        #pragma unroll
        for (int half = 0; half < 2; ++half) {
            int m = m0 + (wm << 5) + (mt << 4) + (lane >> 2) + half * 8;
            size_t ob = (size_t)m * 512;
            #pragma unroll
            for (int nt = 0; nt < 4; ++nt) {
                float hv[2], cv[2];
                #pragma unroll
                for (int e = 0; e < 2; ++e) {
                    int idx = half * 2 + e;
                    float ip = c[0][mt][nt][idx] + (e ? bi2[nt].y : bi2[nt].x);
                    float cp = c[1][mt][nt][idx] + (e ? bc2[nt].y : bc2[nt].x);
                    float op = c[2][mt][nt][idx] + (e ? bo2[nt].y : bo2[nt].x);
                    float ig = 1.0f / (1.0f + __expf(-ip));
                    float og = 1.0f / (1.0f + __expf(-op));
                    float tc = 1.0f - 2.0f / (__expf(2.0f * cp) + 1.0f);
                    float cn2 = ig * tc;
                    float tn = 1.0f - 2.0f / (__expf(2.0f * cn2) + 1.0f);
                    cv[e] = cn2;
                    hv[e] = og * tn;
                }
                *(float2*)(outh + ob + ncb + nt * 8) = *(float2*)hv;
                *(float2*)(outc + ob + ncb + nt * 8) = *(float2*)cv;
            }
        }
    }
}

// ---------------- launcher ----------------
extern "C" void kernel_launch(void* const* d_in, const int* in_sizes, int n_in,
                              void* d_out, int out_size) {
    // 0:x 1:h 2:c_prev 3:Wxi 4:bxi 5:Whi 6:Wxf 7:bxf 8:Whf 9:Wxc 10:bxc 11:Whc 12:Wxo 13:bxo 14:Who
    const float* x   = (const float*)d_in[0];
    const float* h   = (const float*)d_in[1];
    const float* Wxi = (const float*)d_in[3];
    const float* bxi = (const float*)d_in[4];
    const float* Whi = (const float*)d_in[5];
    const float* Wxc = (const float*)d_in[9];
    const float* bxc = (const float*)d_in[10];
    const float* Whc = (const float*)d_in[11];
    const float* Wxo = (const float*)d_in[12];
    const float* bxo = (const float*)d_in[13];
    const float* Who = (const float*)d_in[14];

    float* outh = (float*)d_out;
    float* outc = outh + (size_t)M_SZ * H_SZ;

    const int smem = 1024 + NSTAGE * (int)STAGE_BYTES;   // 115712 -> 2 CTAs/SM
    cudaFuncSetAttribute(lstm_gemm, cudaFuncAttributeMaxDynamicSharedMemorySize, smem);

    prep_ab<<<8192 + 1536, 256>>>(x, h, Wxi, Whi, Wxc, Whc, Wxo, Who);
    lstm_gemm<<<dim3(4, 512), 256, smem>>>(bxi, bxc, bxo, outh, outc);
}